// round 12
// baseline (speedup 1.0000x reference)
#include <cuda_runtime.h>
#include <cuda_bf16.h>

// Distance_26379689132772: dense radius_graph over N=8192 atoms, 128 atoms/mol.
// Output layout (f32): [0, N*N) edge_weight ; [N*N, 2*N*N) mask (0/1).
//
// Fill-path strategy (R8/R11 measurements: memset ~7.3 TB/s > SM stores 6.8):
//   memset W plane ──► memset M plane ──► diagM kernel (exposed, ~1.5us)
//            └─fork──► diagW kernel (hidden under memset M) ──join─┘
// Diag kernels stage the molecule's 128 atoms + |r|^2 in shared memory to
// kill the scattered-gather latency that made the R8 diag kernel 6.6us.

#define NATOMS 8192
#define CUT_HI 5.0f
#define NN     ((size_t)NATOMS * NATOMS)   // floats per plane
#define MOL    128

// One molecule per 4 blocks; block part p covers local rows [p*32, p*32+32).
// 256 threads: 1024 quads per block, 4 per thread.
__global__ __launch_bounds__(256)
void diag_kernel_opt(const float* __restrict__ pos,
                     float*       __restrict__ plane,
                     int want_w)
{
    __shared__ float sp[MOL * 3];   // molecule positions (x,y,z interleaved)
    __shared__ float ssq[MOL];      // |r|^2 per atom

    int mol  = (int)(blockIdx.x >> 2);
    int part = (int)(blockIdx.x & 3u);
    int tid  = (int)threadIdx.x;

    // Coalesced stage: 384 floats = 96 float4.
    const float4* mp4 = (const float4*)(pos + (size_t)mol * MOL * 3);
    if (tid < 96) ((float4*)sp)[tid] = mp4[tid];
    __syncthreads();
    if (tid < MOL) {
        float x = sp[3 * tid], y = sp[3 * tid + 1], z = sp[3 * tid + 2];
        ssq[tid] = x * x + y * y + z * z;
    }
    __syncthreads();

    int molbase = mol * MOL;

    #pragma unroll
    for (int it = 0; it < 4; it++) {
        int q   = it * 256 + tid;          // 0..1023
        int li  = part * 32 + (q >> 5);    // local row 0..127
        int lj0 = (q & 31) * 4;            // local col quad start

        float xi = sp[3 * li], yi = sp[3 * li + 1], zi = sp[3 * li + 2];
        float sqi = ssq[li];

        float v[4];
        #pragma unroll
        for (int k = 0; k < 4; k++) {
            int lj = lj0 + k;
            // Gram trick, matching the reference's arithmetic path.
            float d2 = sqi + ssq[lj]
                     - 2.0f * (xi * sp[3 * lj] + yi * sp[3 * lj + 1] + zi * sp[3 * lj + 2]);
            d2 = fmaxf(d2, 0.0f);
            float d = (d2 > 0.0f) ? sqrtf(d2) : 0.0f;
            bool mask = (li != lj) && (d <= CUT_HI);
            v[k] = mask ? (want_w ? d : 1.0f) : 0.0f;
        }

        size_t off = (size_t)(molbase + li) * NATOMS + (size_t)(molbase + lj0);
        *(float4*)(plane + off) = make_float4(v[0], v[1], v[2], v[3]);
    }
}

extern "C" void kernel_launch(void* const* d_in, const int* in_sizes, int n_in,
                              void* d_out, int out_size)
{
    const float* pos = (const float*)d_in[0];
    float*       W   = (float*)d_out;
    float*       M   = W + NN;

    static cudaStream_t s1 = nullptr;
    static cudaEvent_t  eW, eJ;
    if (s1 == nullptr) {
        cudaStreamCreateWithFlags(&s1, cudaStreamNonBlocking);
        cudaEventCreateWithFlags(&eW, cudaEventDisableTiming);
        cudaEventCreateWithFlags(&eJ, cudaEventDisableTiming);
    }

    // Main stream: fill both planes via the fast memset path.
    cudaMemsetAsync(W, 0, NN * sizeof(float));          // W plane (256MB)
    cudaEventRecord(eW, 0);
    cudaMemsetAsync(M, 0, NN * sizeof(float));          // M plane (256MB)

    // Forked: weight diagonal blocks, hidden under the M-plane memset.
    cudaStreamWaitEvent(s1, eW, 0);
    diag_kernel_opt<<<64 * 4, 256, 0, s1>>>(pos, W, 1);
    cudaEventRecord(eJ, s1);

    // Join, then the only exposed kernel: mask diagonal blocks.
    cudaStreamWaitEvent(0, eJ, 0);
    diag_kernel_opt<<<64 * 4, 256>>>(pos, M, 0);
}

// round 13
// speedup vs baseline: 1.0460x; 1.0460x over previous
#include <cuda_runtime.h>
#include <cuda_bf16.h>

// Distance_26379689132772: dense radius_graph over N=8192 atoms, 128 atoms/mol.
// Output layout (f32): [0, N*N) edge_weight ; [N*N, 2*N*N) mask (0/1).
//
// Two-node serial plan (measured: memset fills at ~7.2 TB/s > SM stores):
//   node 1: cudaMemsetAsync(512MB)  -- zeros both planes
//   node 2: diag_both_kernel        -- overwrites the 64 diagonal 128x128
//           molecule blocks of BOTH planes (16MB total), tuned for latency:
//           float4-packed (x,y,z,|r|^2) atoms in smem, 1024 blocks, 2q/thread.

#define NATOMS 8192
#define CUT_HI 5.0f
#define NN     ((size_t)NATOMS * NATOMS)   // floats per plane
#define MOL    128

// grid = 64 mols * 8 row-parts * 2 planes = 1024 blocks, 256 threads.
// Block covers 16 rows x 128 cols of one molecule's diag block in one plane.
__global__ __launch_bounds__(256)
void diag_both_kernel(const float* __restrict__ pos,
                      float*       __restrict__ out)
{
    __shared__ float4 sa[MOL];      // per-atom (x, y, z, |r|^2)

    unsigned b   = blockIdx.x;
    int plane_id = (int)(b & 1u);             // 0 = weight, 1 = mask
    int part     = (int)((b >> 1) & 7u);      // 0..7 (16-row slab)
    int mol      = (int)(b >> 4);             // 0..63
    int tid      = (int)threadIdx.x;

    // Stage molecule: 128 atoms * 3 floats = 96 float4 coalesced reads,
    // then repack to (x,y,z,sq).
    const float* mp = pos + (size_t)mol * MOL * 3;
    if (tid < MOL) {
        float x = mp[3 * tid], y = mp[3 * tid + 1], z = mp[3 * tid + 2];
        sa[tid] = make_float4(x, y, z, x * x + y * y + z * z);
    }
    __syncthreads();

    float* plane = out + (size_t)plane_id * NN;
    bool want_w  = (plane_id == 0);
    int molbase  = mol * MOL;

    // 16 rows * 32 quad-cols = 512 quads; thread handles q = tid, tid+256.
    #pragma unroll
    for (int it = 0; it < 2; it++) {
        int q   = it * 256 + tid;             // 0..511
        int li  = part * 16 + (q >> 5);       // local row
        int lj0 = (q & 31) * 4;               // local col quad start

        float4 ai = sa[li];

        float v[4];
        #pragma unroll
        for (int k = 0; k < 4; k++) {
            int lj = lj0 + k;
            float4 aj = sa[lj];
            // Gram trick, matching the reference's arithmetic path.
            float d2 = ai.w + aj.w - 2.0f * (ai.x * aj.x + ai.y * aj.y + ai.z * aj.z);
            d2 = fmaxf(d2, 0.0f);
            float d = (d2 > 0.0f) ? sqrtf(d2) : 0.0f;
            bool mask = (li != lj) && (d <= CUT_HI);
            v[k] = mask ? (want_w ? d : 1.0f) : 0.0f;
        }

        size_t off = (size_t)(molbase + li) * NATOMS + (size_t)(molbase + lj0);
        *(float4*)(plane + off) = make_float4(v[0], v[1], v[2], v[3]);
    }
}

extern "C" void kernel_launch(void* const* d_in, const int* in_sizes, int n_in,
                              void* d_out, int out_size)
{
    const float* pos = (const float*)d_in[0];
    float*       out = (float*)d_out;

    // Node 1: zero both planes via the fast fill path (single 512MB memset).
    cudaMemsetAsync(d_out, 0, 2 * NN * sizeof(float));

    // Node 2: overwrite the diagonal molecule blocks of both planes.
    diag_both_kernel<<<64 * 8 * 2, 256>>>(pos, out);
}

// round 14
// speedup vs baseline: 1.1265x; 1.0770x over previous
#include <cuda_runtime.h>
#include <cuda_bf16.h>

// Distance_26379689132772: dense radius_graph over N=8192 atoms, 128 atoms/mol.
// Output layout (f32): [0, N*N)       edge_weight (row-major [i,j])
//                      [N*N, 2*N*N)  mask as 0.0/1.0
//
// FINAL (R4 structure). Pure HBM-store-bound: 512 MB written at the measured
// SM-store ceiling (~6.4 TB/s ncu-active / 6.8 TB/s end-to-end). Verified
// across 5 store layouts + 4 memset-hybrid topologies that no arrangement
// beats this; the DRAM write path is the binder.

#define NATOMS 8192
#define CUT_HI 5.0f
#define QUADS  (NATOMS * NATOMS / 4)   // 16,777,216 float4 per plane

__device__ __forceinline__ void compute_quad(const float* __restrict__ pos,
                                             const int*   __restrict__ batch,
                                             unsigned idx,
                                             float4& ew, float4& mk)
{
    int i = (int)(idx >> 11);            // idx / 2048
    int j = (int)((idx & 2047u) << 2);   // 4*(idx % 2048)

    ew = make_float4(0.f, 0.f, 0.f, 0.f);
    mk = make_float4(0.f, 0.f, 0.f, 0.f);

    int bi = __ldg(batch + i);
    int bj = __ldg(batch + j);           // j..j+3 share a 128-block (j%4==0)

    if (bi == bj) {
        float xi = __ldg(pos + 3 * i + 0);
        float yi = __ldg(pos + 3 * i + 1);
        float zi = __ldg(pos + 3 * i + 2);
        float sqi = xi * xi + yi * yi + zi * zi;

        float w[4], m[4];
        #pragma unroll
        for (int k = 0; k < 4; k++) {
            int jj = j + k;
            float xj = __ldg(pos + 3 * jj + 0);
            float yj = __ldg(pos + 3 * jj + 1);
            float zj = __ldg(pos + 3 * jj + 2);
            float sqj = xj * xj + yj * yj + zj * zj;
            // Gram trick, matching the reference's arithmetic path.
            float d2 = sqi + sqj - 2.0f * (xi * xj + yi * yj + zi * zj);
            d2 = fmaxf(d2, 0.0f);
            float d = (d2 > 0.0f) ? sqrtf(d2) : 0.0f;
            bool mask = (i != jj) && (d <= CUT_HI);
            w[k] = mask ? d : 0.0f;
            m[k] = mask ? 1.0f : 0.0f;
        }
        ew = make_float4(w[0], w[1], w[2], w[3]);
        mk = make_float4(m[0], m[1], m[2], m[3]);
    }
}

__global__ __launch_bounds__(256)
void dist_kernel(const float* __restrict__ pos,
                 const int*   __restrict__ batch,
                 float*       __restrict__ out)
{
    float4* __restrict__ ow = (float4*)out;   // edge_weight plane
    float4* __restrict__ om = ow + QUADS;     // mask plane

    // Block covers 512 consecutive quads; thread t handles t and t+256.
    unsigned base = blockIdx.x * 512u + threadIdx.x;
    unsigned q0 = base;
    unsigned q1 = base + 256u;

    float4 ew0, mk0, ew1, mk1;
    compute_quad(pos, batch, q0, ew0, mk0);
    compute_quad(pos, batch, q1, ew1, mk1);

    ow[q0] = ew0;
    ow[q1] = ew1;
    om[q0] = mk0;
    om[q1] = mk1;
}

extern "C" void kernel_launch(void* const* d_in, const int* in_sizes, int n_in,
                              void* d_out, int out_size)
{
    const float* pos   = (const float*)d_in[0];
    const int*   batch = (const int*)d_in[1];
    float*       out   = (float*)d_out;

    // QUADS / 512 = 32768 blocks, 256 threads each, 2 quads per thread.
    dist_kernel<<<QUADS / 512, 256>>>(pos, batch, out);
}

// round 15
// speedup vs baseline: 1.1311x; 1.0041x over previous
#include <cuda_runtime.h>
#include <cuda_bf16.h>

// Distance_26379689132772: dense radius_graph over N=8192 atoms, 128 atoms/mol.
// Output layout (f32): [0, N*N)       edge_weight (row-major [i,j])
//                      [N*N, 2*N*N)  mask as 0.0/1.0
//
// R4 structure (proven ceiling: 6.4 TB/s, 77.8-78.2us) with ONE change:
// write-through stores (__stwt) to skip L2 dirty-line allocate/writeback
// on this pure write-once 512MB stream.

#define NATOMS 8192
#define CUT_HI 5.0f
#define QUADS  (NATOMS * NATOMS / 4)   // 16,777,216 float4 per plane

__device__ __forceinline__ void compute_quad(const float* __restrict__ pos,
                                             const int*   __restrict__ batch,
                                             unsigned idx,
                                             float4& ew, float4& mk)
{
    int i = (int)(idx >> 11);            // idx / 2048
    int j = (int)((idx & 2047u) << 2);   // 4*(idx % 2048)

    ew = make_float4(0.f, 0.f, 0.f, 0.f);
    mk = make_float4(0.f, 0.f, 0.f, 0.f);

    int bi = __ldg(batch + i);
    int bj = __ldg(batch + j);           // j..j+3 share a 128-block (j%4==0)

    if (bi == bj) {
        float xi = __ldg(pos + 3 * i + 0);
        float yi = __ldg(pos + 3 * i + 1);
        float zi = __ldg(pos + 3 * i + 2);
        float sqi = xi * xi + yi * yi + zi * zi;

        float w[4], m[4];
        #pragma unroll
        for (int k = 0; k < 4; k++) {
            int jj = j + k;
            float xj = __ldg(pos + 3 * jj + 0);
            float yj = __ldg(pos + 3 * jj + 1);
            float zj = __ldg(pos + 3 * jj + 2);
            float sqj = xj * xj + yj * yj + zj * zj;
            // Gram trick, matching the reference's arithmetic path.
            float d2 = sqi + sqj - 2.0f * (xi * xj + yi * yj + zi * zj);
            d2 = fmaxf(d2, 0.0f);
            float d = (d2 > 0.0f) ? sqrtf(d2) : 0.0f;
            bool mask = (i != jj) && (d <= CUT_HI);
            w[k] = mask ? d : 0.0f;
            m[k] = mask ? 1.0f : 0.0f;
        }
        ew = make_float4(w[0], w[1], w[2], w[3]);
        mk = make_float4(m[0], m[1], m[2], m[3]);
    }
}

__global__ __launch_bounds__(256)
void dist_kernel(const float* __restrict__ pos,
                 const int*   __restrict__ batch,
                 float*       __restrict__ out)
{
    float4* __restrict__ ow = (float4*)out;   // edge_weight plane
    float4* __restrict__ om = ow + QUADS;     // mask plane

    // Block covers 512 consecutive quads; thread t handles t and t+256.
    unsigned base = blockIdx.x * 512u + threadIdx.x;
    unsigned q0 = base;
    unsigned q1 = base + 256u;

    float4 ew0, mk0, ew1, mk1;
    compute_quad(pos, batch, q0, ew0, mk0);
    compute_quad(pos, batch, q1, ew1, mk1);

    __stwt(ow + q0, ew0);
    __stwt(ow + q1, ew1);
    __stwt(om + q0, mk0);
    __stwt(om + q1, mk1);
}

extern "C" void kernel_launch(void* const* d_in, const int* in_sizes, int n_in,
                              void* d_out, int out_size)
{
    const float* pos   = (const float*)d_in[0];
    const int*   batch = (const int*)d_in[1];
    float*       out   = (float*)d_out;

    // QUADS / 512 = 32768 blocks, 256 threads each, 2 quads per thread.
    dist_kernel<<<QUADS / 512, 256>>>(pos, batch, out);
}